// round 1
// baseline (speedup 1.0000x reference)
#include <cuda_runtime.h>
#include <cuda_bf16.h>
#include <math_constants.h>

// Problem: N=16384 rows, D=4096 cols, fp32.
// loss = mean_over_rows( logsumexp(logits/alpha) - (logits/alpha)[argmax(labels)] )
// Inputs (metadata order): labels[N*D] f32, logits[N*D] f32, mask (unused), alpha[1] f32.
// Output: 1 x f32.

#define NROWS 16384
#define NCOLS 4096
#define THREADS 256          // 4096 / 256 = 16 elems = 4 float4 per thread per stream

// Scratch: per-row loss (no cudaMalloc allowed -> __device__ global)
__device__ float g_row_loss[NROWS];

__global__ __launch_bounds__(THREADS, 8)
void nce_row_kernel(const float* __restrict__ labels,
                    const float* __restrict__ logits,
                    const float* __restrict__ alpha)
{
    const int row = blockIdx.x;
    const int tid = threadIdx.x;
    const size_t base = (size_t)row * NCOLS;

    const float4* lab4 = reinterpret_cast<const float4*>(labels + base);
    const float4* lgt4 = reinterpret_cast<const float4*>(logits + base);

    const float inv_a = 1.0f / alpha[0];

    // ---- per-thread pass: argmax(labels) + online logsumexp(logits * inv_a) ----
    float bmax = -CUDART_INF_F;   // best label value
    int   bidx = 0;               // its (first) index
    float m = -CUDART_INF_F;      // running max of scaled logits
    float s = 0.0f;               // running sum of exp(x - m)

    #pragma unroll
    for (int i = 0; i < 4; i++) {
        const int j = i * THREADS + tid;         // float4 index, coalesced
        const float4 a = lab4[j];
        const float4 b = lgt4[j];
        const int e0 = j * 4;

        // argmax over the 4 label components (first-index tie-break via strict >)
        if (a.x > bmax) { bmax = a.x; bidx = e0 + 0; }
        if (a.y > bmax) { bmax = a.y; bidx = e0 + 1; }
        if (a.z > bmax) { bmax = a.z; bidx = e0 + 2; }
        if (a.w > bmax) { bmax = a.w; bidx = e0 + 3; }

        // online logsumexp over the 4 scaled logit components
        float x;
        x = b.x * inv_a;
        if (x > m) { s = s * __expf(m - x) + 1.0f; m = x; } else { s += __expf(x - m); }
        x = b.y * inv_a;
        if (x > m) { s = s * __expf(m - x) + 1.0f; m = x; } else { s += __expf(x - m); }
        x = b.z * inv_a;
        if (x > m) { s = s * __expf(m - x) + 1.0f; m = x; } else { s += __expf(x - m); }
        x = b.w * inv_a;
        if (x > m) { s = s * __expf(m - x) + 1.0f; m = x; } else { s += __expf(x - m); }
    }

    // ---- warp reduction (shuffle) ----
    #pragma unroll
    for (int off = 16; off > 0; off >>= 1) {
        // logsumexp combine
        const float om = __shfl_down_sync(0xFFFFFFFFu, m, off);
        const float os = __shfl_down_sync(0xFFFFFFFFu, s, off);
        const float nm = fmaxf(m, om);
        s = s * __expf(m - nm) + os * __expf(om - nm);
        m = nm;
        // argmax combine (first-index tie-break: lower index wins on equality)
        const float ov = __shfl_down_sync(0xFFFFFFFFu, bmax, off);
        const int   oi = __shfl_down_sync(0xFFFFFFFFu, bidx, off);
        if (ov > bmax || (ov == bmax && oi < bidx)) { bmax = ov; bidx = oi; }
    }

    // ---- cross-warp reduction via shared ----
    __shared__ float sh_m[8], sh_s[8], sh_v[8];
    __shared__ int   sh_i[8];
    const int wid = tid >> 5;
    const int lid = tid & 31;
    if (lid == 0) { sh_m[wid] = m; sh_s[wid] = s; sh_v[wid] = bmax; sh_i[wid] = bidx; }
    __syncthreads();

    if (tid == 0) {
        float fm = sh_m[0], fs = sh_s[0];
        float fv = sh_v[0];
        int   fi = sh_i[0];
        #pragma unroll
        for (int w = 1; w < 8; w++) {
            const float om = sh_m[w], os = sh_s[w];
            const float nm = fmaxf(fm, om);
            fs = fs * __expf(fm - nm) + os * __expf(om - nm);
            fm = nm;
            const float ov = sh_v[w];
            const int   oi = sh_i[w];
            if (ov > fv || (ov == fv && oi < fi)) { fv = ov; fi = oi; }
        }
        // positive scaled logit: single re-read, L2-hot (row just streamed)
        const float pos = logits[base + fi] * inv_a;
        g_row_loss[row] = fm + __logf(fs) - pos;
    }
}

// Deterministic mean over 16384 per-row losses: fixed per-thread order + fixed tree.
__global__ __launch_bounds__(1024)
void nce_reduce_kernel(float* __restrict__ out)
{
    __shared__ float sh[1024];
    const int tid = threadIdx.x;
    float acc = 0.0f;
    #pragma unroll
    for (int i = 0; i < NROWS / 1024; i++)
        acc += g_row_loss[i * 1024 + tid];
    sh[tid] = acc;
    __syncthreads();
    #pragma unroll
    for (int stride = 512; stride > 0; stride >>= 1) {
        if (tid < stride) sh[tid] += sh[tid + stride];
        __syncthreads();
    }
    if (tid == 0) out[0] = sh[0] * (1.0f / (float)NROWS);
}

extern "C" void kernel_launch(void* const* d_in, const int* in_sizes, int n_in,
                              void* d_out, int out_size)
{
    const float* labels = (const float*)d_in[0];
    const float* logits = (const float*)d_in[1];
    // d_in[2] = mask (bool) -- unused by the math, never read.
    const float* alpha  = (const float*)d_in[3];
    float* out = (float*)d_out;

    nce_row_kernel<<<NROWS, THREADS>>>(labels, logits, alpha);
    nce_reduce_kernel<<<1, 1024>>>(out);
}